// round 1
// baseline (speedup 1.0000x reference)
#include <cuda_runtime.h>
#include <math.h>

// Problem constants
#define SEQ   2048
#define DMODEL 1024
#define NHEAD 16
#define DH    64
#define BR    64
#define BC    64
#define STRIDE 68          // padded row stride (floats) for smem tiles
#define NTHREADS 256

#define NEG_BIG (-1.0e30f)

__global__ __launch_bounds__(NTHREADS, 2)
void alibi_flash_fp32_kernel(const float* __restrict__ q,
                             const float* __restrict__ k,
                             const float* __restrict__ v,
                             float* __restrict__ out)
{
    extern __shared__ float sm[];
    float* sQ = sm;                    // [64][STRIDE] row-major (t, d)
    float* sK = sQ + BR * STRIDE;      // [64][STRIDE] row-major (s, d)
    float* sV = sK + BC * STRIDE;      // [64][STRIDE] transposed: (e, s)
    float* sP = sV + DH * STRIDE;      // [64][STRIDE] row-major (t, s)

    const int bh = blockIdx.x;            // 0..31
    const int b  = bh >> 4;
    const int h  = bh & 15;
    const int qt = 31 - (int)blockIdx.y;  // heavy tiles first
    const int tid = threadIdx.x;
    const int tr = tid >> 4;              // 0..15
    const int tc = tid & 15;              // 0..15

    const float mh = exp2f(-0.5f * (float)(h + 1));   // ALiBi slope
    const int t0 = qt * BR;

    // ---- Load Q tile [64][64], coalesced float4 ----
    {
        const float* qbase = q + ((size_t)b * SEQ + t0) * DMODEL + h * DH;
        for (int i = tid; i < BR * 16; i += NTHREADS) {
            int t  = i >> 4;
            int d4 = (i & 15) << 2;
            float4 val = *(const float4*)(qbase + (size_t)t * DMODEL + d4);
            float* dst = sQ + t * STRIDE + d4;
            dst[0] = val.x; dst[1] = val.y; dst[2] = val.z; dst[3] = val.w;
        }
    }

    float Oacc[4][4];
    float m_i[4], l_i[4];
#pragma unroll
    for (int i = 0; i < 4; ++i) {
        m_i[i] = NEG_BIG;
        l_i[i] = 0.0f;
#pragma unroll
        for (int j = 0; j < 4; ++j) Oacc[i][j] = 0.0f;
    }

    for (int st = 0; st <= qt; ++st) {
        __syncthreads();   // previous iteration done using sK/sV/sP

        // ---- Load K tile [64][64] row-major, coalesced ----
        {
            const float* kbase = k + ((size_t)b * SEQ + st * BC) * DMODEL + h * DH;
            for (int i = tid; i < BC * 16; i += NTHREADS) {
                int s  = i >> 4;
                int d4 = (i & 15) << 2;
                float4 val = *(const float4*)(kbase + (size_t)s * DMODEL + d4);
                float* dst = sK + s * STRIDE + d4;
                dst[0] = val.x; dst[1] = val.y; dst[2] = val.z; dst[3] = val.w;
            }
        }
        // ---- Load V tile transposed -> sV[e][s] (conflict-free STS) ----
        {
            const float* vbase = v + ((size_t)b * SEQ + st * BC) * DMODEL + h * DH;
#pragma unroll
            for (int it = 0; it < 4; ++it) {
                int i  = tid + it * NTHREADS;
                int s  = i & 63;
                int e4 = (i >> 6) << 2;
                float4 val = *(const float4*)(vbase + (size_t)s * DMODEL + e4);
                sV[(e4 + 0) * STRIDE + s] = val.x;
                sV[(e4 + 1) * STRIDE + s] = val.y;
                sV[(e4 + 2) * STRIDE + s] = val.z;
                sV[(e4 + 3) * STRIDE + s] = val.w;
            }
        }
        __syncthreads();

        // ---- S = (Q K^T) * 1/8 + alibi, causal mask ----
        float acc[4][4];
#pragma unroll
        for (int i = 0; i < 4; ++i)
#pragma unroll
            for (int j = 0; j < 4; ++j) acc[i][j] = 0.0f;

#pragma unroll 4
        for (int d4 = 0; d4 < DH; d4 += 4) {
            float4 q4[4], k4[4];
#pragma unroll
            for (int i = 0; i < 4; ++i)
                q4[i] = *(const float4*)(sQ + (tr + 16 * i) * STRIDE + d4);
#pragma unroll
            for (int j = 0; j < 4; ++j)
                k4[j] = *(const float4*)(sK + (tc + 16 * j) * STRIDE + d4);
#pragma unroll
            for (int i = 0; i < 4; ++i)
#pragma unroll
                for (int j = 0; j < 4; ++j) {
                    acc[i][j] = fmaf(q4[i].x, k4[j].x, acc[i][j]);
                    acc[i][j] = fmaf(q4[i].y, k4[j].y, acc[i][j]);
                    acc[i][j] = fmaf(q4[i].z, k4[j].z, acc[i][j]);
                    acc[i][j] = fmaf(q4[i].w, k4[j].w, acc[i][j]);
                }
        }

        const int s0 = st * BC;
#pragma unroll
        for (int i = 0; i < 4; ++i) {
            const int trow = t0 + tr + 16 * i;
#pragma unroll
            for (int j = 0; j < 4; ++j) {
                const int scol = s0 + tc + 16 * j;
                float sc = acc[i][j] * 0.125f + (float)(scol - trow) * mh;
                if (scol > trow) sc = NEG_BIG;
                acc[i][j] = sc;
            }
        }

        // ---- online softmax (row stats shared across 16-lane tc groups) ----
        float rowmax[4], rowsum[4], scale[4];
#pragma unroll
        for (int i = 0; i < 4; ++i) {
            float mx = acc[i][0];
            mx = fmaxf(mx, acc[i][1]);
            mx = fmaxf(mx, acc[i][2]);
            mx = fmaxf(mx, acc[i][3]);
#pragma unroll
            for (int off = 8; off >= 1; off >>= 1)
                mx = fmaxf(mx, __shfl_xor_sync(0xffffffffu, mx, off));
            float mnew = fmaxf(m_i[i], mx);
            scale[i] = __expf(m_i[i] - mnew);
            m_i[i] = mnew;

            float rs = 0.0f;
#pragma unroll
            for (int j = 0; j < 4; ++j) {
                float p = __expf(acc[i][j] - mnew);
                acc[i][j] = p;
                rs += p;
            }
#pragma unroll
            for (int off = 8; off >= 1; off >>= 1)
                rs += __shfl_xor_sync(0xffffffffu, rs, off);
            rowsum[i] = rs;
        }
#pragma unroll
        for (int i = 0; i < 4; ++i) {
            l_i[i] = l_i[i] * scale[i] + rowsum[i];
#pragma unroll
            for (int j = 0; j < 4; ++j) Oacc[i][j] *= scale[i];
        }

        // ---- write P to smem ----
#pragma unroll
        for (int i = 0; i < 4; ++i)
#pragma unroll
            for (int j = 0; j < 4; ++j)
                sP[(tr + 16 * i) * STRIDE + (tc + 16 * j)] = acc[i][j];
        __syncthreads();

        // ---- O += P V  (P row-major, V transposed) ----
#pragma unroll 4
        for (int s4 = 0; s4 < BC; s4 += 4) {
            float4 p4[4], v4[4];
#pragma unroll
            for (int i = 0; i < 4; ++i)
                p4[i] = *(const float4*)(sP + (tr + 16 * i) * STRIDE + s4);
#pragma unroll
            for (int j = 0; j < 4; ++j)
                v4[j] = *(const float4*)(sV + (tc + 16 * j) * STRIDE + s4);
#pragma unroll
            for (int i = 0; i < 4; ++i)
#pragma unroll
                for (int j = 0; j < 4; ++j) {
                    Oacc[i][j] = fmaf(p4[i].x, v4[j].x, Oacc[i][j]);
                    Oacc[i][j] = fmaf(p4[i].y, v4[j].y, Oacc[i][j]);
                    Oacc[i][j] = fmaf(p4[i].z, v4[j].z, Oacc[i][j]);
                    Oacc[i][j] = fmaf(p4[i].w, v4[j].w, Oacc[i][j]);
                }
        }
    }

    // ---- epilogue: normalize and store ----
    float* obase = out + ((size_t)b * SEQ + t0) * DMODEL + h * DH;
#pragma unroll
    for (int i = 0; i < 4; ++i) {
        const float inv = 1.0f / l_i[i];
#pragma unroll
        for (int j = 0; j < 4; ++j)
            obase[(size_t)(tr + 16 * i) * DMODEL + (tc + 16 * j)] = Oacc[i][j] * inv;
    }
}

extern "C" void kernel_launch(void* const* d_in, const int* in_sizes, int n_in,
                              void* d_out, int out_size)
{
    const float* q = (const float*)d_in[0];
    const float* k = (const float*)d_in[1];
    const float* v = (const float*)d_in[2];
    float* out = (float*)d_out;

    const int smem_bytes = 4 * 64 * STRIDE * (int)sizeof(float); // 69632
    static bool attr_set = false;
    if (!attr_set) {
        cudaFuncSetAttribute(alibi_flash_fp32_kernel,
                             cudaFuncAttributeMaxDynamicSharedMemorySize, smem_bytes);
        attr_set = true;
    }

    dim3 grid(32 /*b*h*/, 32 /*q tiles*/);
    alibi_flash_fp32_kernel<<<grid, NTHREADS, smem_bytes>>>(q, k, v, out);
}

// round 3
// speedup vs baseline: 3.4239x; 3.4239x over previous
#include <cuda_runtime.h>
#include <cuda_bf16.h>
#include <stdint.h>

#define SEQ     2048
#define DMODEL  1024
#define NHEAD   16
#define DH      64
#define BR      64
#define BC      64
#define NT      128
#define STRB    144        // smem row stride in bytes (72 bf16)

// smem byte offsets (each tile 64 rows x 144B = 9216B)
#define SM_QHI  0
#define SM_QLO  9216
#define SM_KHI  18432
#define SM_KLO  27648
#define SM_VHI  36864
#define SM_VLO  46080
#define SM_TOTAL 55296

__device__ __forceinline__ uint32_t smem_u32(const void* p) {
    uint32_t a;
    asm("{ .reg .u64 t; cvta.to.shared.u64 t, %1; cvt.u32.u64 %0, t; }" : "=r"(a) : "l"(p));
    return a;
}

__device__ __forceinline__ void ldsm4(uint32_t* r, uint32_t addr) {
    asm volatile("ldmatrix.sync.aligned.m8n8.x4.shared.b16 {%0,%1,%2,%3}, [%4];"
                 : "=r"(r[0]), "=r"(r[1]), "=r"(r[2]), "=r"(r[3]) : "r"(addr));
}
__device__ __forceinline__ void ldsm4t(uint32_t* r, uint32_t addr) {
    asm volatile("ldmatrix.sync.aligned.m8n8.x4.trans.shared.b16 {%0,%1,%2,%3}, [%4];"
                 : "=r"(r[0]), "=r"(r[1]), "=r"(r[2]), "=r"(r[3]) : "r"(addr));
}
__device__ __forceinline__ void mma16816(float* d, const uint32_t* a, const uint32_t* b) {
    asm volatile("mma.sync.aligned.m16n8k16.row.col.f32.bf16.bf16.f32 "
                 "{%0,%1,%2,%3}, {%4,%5,%6,%7}, {%8,%9}, {%0,%1,%2,%3};"
                 : "+f"(d[0]), "+f"(d[1]), "+f"(d[2]), "+f"(d[3])
                 : "r"(a[0]), "r"(a[1]), "r"(a[2]), "r"(a[3]), "r"(b[0]), "r"(b[1]));
}

// split two fp32 into packed bf16 hi pair + bf16 lo (residual) pair; elem0 in low half
__device__ __forceinline__ void split2(float x0, float x1, uint32_t& hi, uint32_t& lo) {
    asm("cvt.rn.bf16x2.f32 %0, %1, %2;" : "=r"(hi) : "f"(x1), "f"(x0));
    float h0 = __uint_as_float(hi << 16);
    float h1 = __uint_as_float(hi & 0xFFFF0000u);
    float r0 = x0 - h0, r1 = x1 - h1;
    asm("cvt.rn.bf16x2.f32 %0, %1, %2;" : "=r"(lo) : "f"(r1), "f"(r0));
}

// load [64 x 64] fp32 tile (row stride DMODEL) -> split bf16 hi/lo smem tiles
__device__ __forceinline__ void load_split64(const float* __restrict__ g, char* sm_,
                                             int off_hi, int off_lo, int tid) {
#pragma unroll
    for (int it = 0; it < 8; ++it) {
        int i  = tid + it * NT;
        int r  = i >> 4;
        int c4 = (i & 15) << 2;
        float4 v = *(const float4*)(g + (size_t)r * DMODEL + c4);
        uint32_t h0, l0, h1, l1;
        split2(v.x, v.y, h0, l0);
        split2(v.z, v.w, h1, l1);
        int off = r * STRB + c4 * 2;
        *(uint2*)(sm_ + off_hi + off) = make_uint2(h0, h1);
        *(uint2*)(sm_ + off_lo + off) = make_uint2(l0, l1);
    }
}

__global__ __launch_bounds__(NT, 3)
void alibi_flash_hmma_kernel(const float* __restrict__ q,
                             const float* __restrict__ k,
                             const float* __restrict__ v,
                             float* __restrict__ out)
{
    extern __shared__ char smem[];
    const uint32_t sb = smem_u32(smem);
    const int tid  = threadIdx.x;
    const int lane = tid & 31;
    const int warp = tid >> 5;
    const int bh = blockIdx.x;
    const int b  = bh >> 4;
    const int h  = bh & 15;
    const int qt = 31 - (int)blockIdx.y;     // heavy tiles first
    const int t0 = qt * BR;
    const int m0 = warp * 16;                // warp's q-row block
    const float mh = exp2f(-0.5f * (float)(h + 1));

    // ldmatrix lane address components
    const int a_row  = lane & 15;                          // A (Q) and V pattern
    const int a_col8 = (lane >> 4) << 3;                   // 0 or 8
    const int k_row  = (lane & 7) + ((lane & 16) ? 8 : 0); // K pattern
    const int k_col8 = (lane & 8) ? 8 : 0;

    // softmax row coordinates (c-fragment layout)
    const int trowA = t0 + m0 + (lane >> 2);
    const int trowB = trowA + 8;
    const int cb    = (lane & 3) << 1;

    // ---- load Q tile (split bf16) ----
    load_split64(q + ((size_t)b * SEQ + t0) * DMODEL + h * DH, smem, SM_QHI, SM_QLO, tid);

    float oa[8][4];
#pragma unroll
    for (int j = 0; j < 8; ++j)
#pragma unroll
        for (int e = 0; e < 4; ++e) oa[j][e] = 0.0f;
    float lA = 0.0f, lB = 0.0f;

    for (int st = 0; st <= qt; ++st) {
        if (st) __syncthreads();     // previous iteration done reading sK/sV
        load_split64(k + ((size_t)b * SEQ + st * BC) * DMODEL + h * DH,
                     smem, SM_KHI, SM_KLO, tid);
        load_split64(v + ((size_t)b * SEQ + st * BC) * DMODEL + h * DH,
                     smem, SM_VHI, SM_VLO, tid);
        __syncthreads();

        // ================= S = Q K^T (3 split products) =================
        float sa[8][4];
#pragma unroll
        for (int j = 0; j < 8; ++j)
#pragma unroll
            for (int e = 0; e < 4; ++e) sa[j][e] = 0.0f;

#pragma unroll
        for (int kt = 0; kt < 4; ++kt) {
            uint32_t qh[4], ql[4];
            const int acol = kt * 16 + a_col8;
            ldsm4(qh, sb + SM_QHI + (m0 + a_row) * STRB + acol * 2);
            ldsm4(ql, sb + SM_QLO + (m0 + a_row) * STRB + acol * 2);
#pragma unroll
            for (int jp = 0; jp < 4; ++jp) {
                uint32_t kh[4], kl[4];
                const int koff = (jp * 16 + k_row) * STRB + (kt * 16 + k_col8) * 2;
                ldsm4(kh, sb + SM_KHI + koff);
                ldsm4(kl, sb + SM_KLO + koff);
                mma16816(sa[2 * jp],     qh, kh);
                mma16816(sa[2 * jp + 1], qh, kh + 2);
                mma16816(sa[2 * jp],     qh, kl);
                mma16816(sa[2 * jp + 1], qh, kl + 2);
                mma16816(sa[2 * jp],     ql, kh);
                mma16816(sa[2 * jp + 1], ql, kh + 2);
            }
        }

        // ============ P = exp(S/8 + alibi - 8), pack to bf16 hi/lo ============
        const int s0 = st * BC;
        uint32_t ph[8][2], pl[8][2];
#pragma unroll
        for (int j = 0; j < 8; ++j) {
            const int sc = s0 + j * 8 + cb;
            float x00 = fmaf(sa[j][0], 0.125f, (float)(sc     - trowA) * mh - 8.0f);
            float x01 = fmaf(sa[j][1], 0.125f, (float)(sc + 1 - trowA) * mh - 8.0f);
            float x10 = fmaf(sa[j][2], 0.125f, (float)(sc     - trowB) * mh - 8.0f);
            float x11 = fmaf(sa[j][3], 0.125f, (float)(sc + 1 - trowB) * mh - 8.0f);
            float p00 = (sc     <= trowA) ? __expf(x00) : 0.0f;
            float p01 = (sc + 1 <= trowA) ? __expf(x01) : 0.0f;
            float p10 = (sc     <= trowB) ? __expf(x10) : 0.0f;
            float p11 = (sc + 1 <= trowB) ? __expf(x11) : 0.0f;
            lA += p00 + p01;
            lB += p10 + p11;
            split2(p00, p01, ph[j][0], pl[j][0]);
            split2(p10, p11, ph[j][1], pl[j][1]);
        }

        // ================= O += P V (3 split products) =================
#pragma unroll
        for (int kt = 0; kt < 4; ++kt) {
            uint32_t pah[4] = { ph[2 * kt][0], ph[2 * kt][1], ph[2 * kt + 1][0], ph[2 * kt + 1][1] };
            uint32_t pal[4] = { pl[2 * kt][0], pl[2 * kt][1], pl[2 * kt + 1][0], pl[2 * kt + 1][1] };
#pragma unroll
            for (int jp = 0; jp < 4; ++jp) {
                uint32_t vh[4], vl[4];
                const int voff = (kt * 16 + a_row) * STRB + (jp * 16 + a_col8) * 2;
                ldsm4t(vh, sb + SM_VHI + voff);
                ldsm4t(vl, sb + SM_VLO + voff);
                mma16816(oa[2 * jp],     pah, vh);
                mma16816(oa[2 * jp + 1], pah, vh + 2);
                mma16816(oa[2 * jp],     pah, vl);
                mma16816(oa[2 * jp + 1], pah, vl + 2);
                mma16816(oa[2 * jp],     pal, vh);
                mma16816(oa[2 * jp + 1], pal, vh + 2);
            }
        }
    }

    // ---- normalize and store ----
    lA += __shfl_xor_sync(0xffffffffu, lA, 1);
    lA += __shfl_xor_sync(0xffffffffu, lA, 2);
    lB += __shfl_xor_sync(0xffffffffu, lB, 1);
    lB += __shfl_xor_sync(0xffffffffu, lB, 2);
    const float invA = 1.0f / lA;
    const float invB = 1.0f / lB;

    float* obA = out + ((size_t)b * SEQ + trowA) * DMODEL + h * DH;
    float* obB = out + ((size_t)b * SEQ + trowB) * DMODEL + h * DH;
#pragma unroll
    for (int j = 0; j < 8; ++j) {
        const int e = j * 8 + cb;
        *(float2*)(obA + e) = make_float2(oa[j][0] * invA, oa[j][1] * invA);
        *(float2*)(obB + e) = make_float2(oa[j][2] * invB, oa[j][3] * invB);
    }
}

extern "C" void kernel_launch(void* const* d_in, const int* in_sizes, int n_in,
                              void* d_out, int out_size)
{
    const float* q = (const float*)d_in[0];
    const float* k = (const float*)d_in[1];
    const float* v = (const float*)d_in[2];
    float* out = (float*)d_out;

    static bool attr_set = false;
    if (!attr_set) {
        cudaFuncSetAttribute(alibi_flash_hmma_kernel,
                             cudaFuncAttributeMaxDynamicSharedMemorySize, SM_TOTAL);
        attr_set = true;
    }
    dim3 grid(32 /* b*h */, 32 /* q tiles */);
    alibi_flash_hmma_kernel<<<grid, NT, SM_TOTAL>>>(q, k, v, out);
}

// round 4
// speedup vs baseline: 3.4795x; 1.0163x over previous
#include <cuda_runtime.h>
#include <cuda_bf16.h>
#include <stdint.h>

#define SEQ     2048
#define DMODEL  1024
#define NHEAD   16
#define DH      64
#define BR      128        // q rows per CTA (32 per warp)
#define BC      64         // kv rows per tile
#define NT      128
#define STRB    144        // smem row stride bytes (72 bf16)

// smem byte offsets
#define SM_QHI  0
#define SM_QLO  18432
#define SM_KHI  36864
#define SM_KLO  46080
#define SM_VHI  55296
#define SM_VLO  64512
#define SM_TOTAL 73728

#define C1  0.18033688f     // 0.125 * log2(e)
#define C0  11.541560f      // 8 * log2(e)

__device__ __forceinline__ uint32_t smem_u32(const void* p) {
    uint32_t a;
    asm("{ .reg .u64 t; cvta.to.shared.u64 t, %1; cvt.u32.u64 %0, t; }" : "=r"(a) : "l"(p));
    return a;
}
__device__ __forceinline__ void ldsm4(uint32_t* r, uint32_t addr) {
    asm volatile("ldmatrix.sync.aligned.m8n8.x4.shared.b16 {%0,%1,%2,%3}, [%4];"
                 : "=r"(r[0]), "=r"(r[1]), "=r"(r[2]), "=r"(r[3]) : "r"(addr));
}
__device__ __forceinline__ void ldsm4t(uint32_t* r, uint32_t addr) {
    asm volatile("ldmatrix.sync.aligned.m8n8.x4.trans.shared.b16 {%0,%1,%2,%3}, [%4];"
                 : "=r"(r[0]), "=r"(r[1]), "=r"(r[2]), "=r"(r[3]) : "r"(addr));
}
__device__ __forceinline__ void mma16816(float* d, const uint32_t* a, const uint32_t* b) {
    asm volatile("mma.sync.aligned.m16n8k16.row.col.f32.bf16.bf16.f32 "
                 "{%0,%1,%2,%3}, {%4,%5,%6,%7}, {%8,%9}, {%0,%1,%2,%3};"
                 : "+f"(d[0]), "+f"(d[1]), "+f"(d[2]), "+f"(d[3])
                 : "r"(a[0]), "r"(a[1]), "r"(a[2]), "r"(a[3]), "r"(b[0]), "r"(b[1]));
}
__device__ __forceinline__ void split2(float x0, float x1, uint32_t& hi, uint32_t& lo) {
    asm("cvt.rn.bf16x2.f32 %0, %1, %2;" : "=r"(hi) : "f"(x1), "f"(x0));
    float h0 = __uint_as_float(hi << 16);
    float h1 = __uint_as_float(hi & 0xFFFF0000u);
    float r0 = x0 - h0, r1 = x1 - h1;
    asm("cvt.rn.bf16x2.f32 %0, %1, %2;" : "=r"(lo) : "f"(r1), "f"(r0));
}

// load [ROWS x 64] fp32 tile (row stride DMODEL) -> split bf16 hi/lo smem tiles
template<int ROWS>
__device__ __forceinline__ void load_split(const float* __restrict__ g, char* sm_,
                                           int off_hi, int off_lo, int tid) {
#pragma unroll
    for (int it = 0; it < ROWS / 8; ++it) {
        int i  = tid + it * NT;
        int r  = i >> 4;
        int c4 = (i & 15) << 2;
        float4 v = *(const float4*)(g + (size_t)r * DMODEL + c4);
        uint32_t h0, l0, h1, l1;
        split2(v.x, v.y, h0, l0);
        split2(v.z, v.w, h1, l1);
        int off = r * STRB + c4 * 2;
        *(uint2*)(sm_ + off_hi + off) = make_uint2(h0, h1);
        *(uint2*)(sm_ + off_lo + off) = make_uint2(l0, l1);
    }
}

// epilogue for one 16-row block: P = exp2(S*C1 + d*mh2 - C0), pack bf16 hi/lo
#define EPILOGUE(sa, ph, pl, trowA, lA, lB, DOMASK)                                   \
    {                                                                                  \
        const float dA = (float)(s0 + cb - (trowA));                                   \
        const float dB = dA - 8.0f;                                                    \
        _Pragma("unroll")                                                              \
        for (int j = 0; j < 8; ++j) {                                                  \
            const float fj = (float)(8 * j);                                           \
            const float eA = fmaf(dA + fj, mh2, -C0);                                  \
            const float eB = fmaf(dB + fj, mh2, -C0);                                  \
            float p00 = exp2f(fmaf(sa[j][0], C1, eA));                                 \
            float p01 = exp2f(fmaf(sa[j][1], C1, eA + mh2));                           \
            float p10 = exp2f(fmaf(sa[j][2], C1, eB));                                 \
            float p11 = exp2f(fmaf(sa[j][3], C1, eB + mh2));                           \
            if (DOMASK) {                                                              \
                const int sc = s0 + 8 * j + cb;                                        \
                if (sc     > (trowA))     p00 = 0.0f;                                  \
                if (sc + 1 > (trowA))     p01 = 0.0f;                                  \
                if (sc     > (trowA) + 8) p10 = 0.0f;                                  \
                if (sc + 1 > (trowA) + 8) p11 = 0.0f;                                  \
            }                                                                          \
            lA += p00 + p01;                                                           \
            lB += p10 + p11;                                                           \
            split2(p00, p01, ph[j][0], pl[j][0]);                                      \
            split2(p10, p11, ph[j][1], pl[j][1]);                                      \
        }                                                                              \
    }

__global__ __launch_bounds__(NT, 2)
void alibi_flash_hmma2_kernel(const float* __restrict__ q,
                              const float* __restrict__ k,
                              const float* __restrict__ v,
                              float* __restrict__ out)
{
    extern __shared__ char smem[];
    const uint32_t sb = smem_u32(smem);
    const int tid  = threadIdx.x;
    const int lane = tid & 31;
    const int warp = tid >> 5;
    const int bh = blockIdx.x;
    const int b  = bh >> 4;
    const int h  = bh & 15;
    const int qt = 15 - (int)blockIdx.y;     // heavy tiles first
    const int t0 = qt * BR;
    const int m0 = warp * 32;                // warp's 32-row q block
    const float mh  = exp2f(-0.5f * (float)(h + 1));
    const float mh2 = mh * 1.44269504f;

    // ldmatrix lane address components
    const int a_row  = lane & 15;
    const int a_col8 = (lane >> 4) << 3;
    const int k_row  = (lane & 7) + ((lane & 16) ? 8 : 0);
    const int k_col8 = (lane & 8) ? 8 : 0;

    const int trow0 = t0 + m0 + (lane >> 2);       // block0 row A
    const int trow1 = trow0 + 16;                  // block1 row A
    const int cb    = (lane & 3) << 1;

    // ---- load Q tile (128 rows, split bf16) ----
    load_split<128>(q + ((size_t)b * SEQ + t0) * DMODEL + h * DH, smem, SM_QHI, SM_QLO, tid);

    float oa0[8][4], oa1[8][4];
#pragma unroll
    for (int j = 0; j < 8; ++j)
#pragma unroll
        for (int e = 0; e < 4; ++e) { oa0[j][e] = 0.0f; oa1[j][e] = 0.0f; }
    float l0A = 0.0f, l0B = 0.0f, l1A = 0.0f, l1B = 0.0f;

    const int nkv = 2 * qt + 2;
    for (int st = 0; st < nkv; ++st) {
        if (st) __syncthreads();
        load_split<64>(k + ((size_t)b * SEQ + st * BC) * DMODEL + h * DH,
                       smem, SM_KHI, SM_KLO, tid);
        load_split<64>(v + ((size_t)b * SEQ + st * BC) * DMODEL + h * DH,
                       smem, SM_VHI, SM_VLO, tid);
        __syncthreads();

        // ================= S = Q K^T (3 split products, 2 row blocks) =================
        float sa0[8][4], sa1[8][4];
#pragma unroll
        for (int j = 0; j < 8; ++j)
#pragma unroll
            for (int e = 0; e < 4; ++e) { sa0[j][e] = 0.0f; sa1[j][e] = 0.0f; }

#pragma unroll
        for (int kt = 0; kt < 4; ++kt) {
            uint32_t qh0[4], ql0[4], qh1[4], ql1[4];
            const uint32_t qoff = (uint32_t)((m0 + a_row) * STRB + (kt * 16 + a_col8) * 2);
            ldsm4(qh0, sb + SM_QHI + qoff);
            ldsm4(ql0, sb + SM_QLO + qoff);
            ldsm4(qh1, sb + SM_QHI + qoff + 16 * STRB);
            ldsm4(ql1, sb + SM_QLO + qoff + 16 * STRB);
#pragma unroll
            for (int jp = 0; jp < 4; ++jp) {
                uint32_t kh[4], kl[4];
                const uint32_t koff = (uint32_t)((jp * 16 + k_row) * STRB + (kt * 16 + k_col8) * 2);
                ldsm4(kh, sb + SM_KHI + koff);
                ldsm4(kl, sb + SM_KLO + koff);
                mma16816(sa0[2 * jp],     qh0, kh);
                mma16816(sa0[2 * jp + 1], qh0, kh + 2);
                mma16816(sa1[2 * jp],     qh1, kh);
                mma16816(sa1[2 * jp + 1], qh1, kh + 2);
                mma16816(sa0[2 * jp],     qh0, kl);
                mma16816(sa0[2 * jp + 1], qh0, kl + 2);
                mma16816(sa1[2 * jp],     qh1, kl);
                mma16816(sa1[2 * jp + 1], qh1, kl + 2);
                mma16816(sa0[2 * jp],     ql0, kh);
                mma16816(sa0[2 * jp + 1], ql0, kh + 2);
                mma16816(sa1[2 * jp],     ql1, kh);
                mma16816(sa1[2 * jp + 1], ql1, kh + 2);
            }
        }

        // ============ epilogue: P = exp(...), pack to bf16 hi/lo ============
        const int s0 = st * BC;
        uint32_t ph0[8][2], pl0[8][2], ph1[8][2], pl1[8][2];
        if (st < 2 * qt) {     // fully-causal tile: no masking needed
            EPILOGUE(sa0, ph0, pl0, trow0, l0A, l0B, false)
            EPILOGUE(sa1, ph1, pl1, trow1, l1A, l1B, false)
        } else {
            EPILOGUE(sa0, ph0, pl0, trow0, l0A, l0B, true)
            EPILOGUE(sa1, ph1, pl1, trow1, l1A, l1B, true)
        }

        // ================= O += P V (3 split products, 2 row blocks) =================
#pragma unroll
        for (int kt = 0; kt < 4; ++kt) {
            uint32_t a0h[4] = { ph0[2*kt][0], ph0[2*kt][1], ph0[2*kt+1][0], ph0[2*kt+1][1] };
            uint32_t a0l[4] = { pl0[2*kt][0], pl0[2*kt][1], pl0[2*kt+1][0], pl0[2*kt+1][1] };
            uint32_t a1h[4] = { ph1[2*kt][0], ph1[2*kt][1], ph1[2*kt+1][0], ph1[2*kt+1][1] };
            uint32_t a1l[4] = { pl1[2*kt][0], pl1[2*kt][1], pl1[2*kt+1][0], pl1[2*kt+1][1] };
#pragma unroll
            for (int jp = 0; jp < 4; ++jp) {
                uint32_t vh[4], vl[4];
                const uint32_t voff = (uint32_t)((kt * 16 + a_row) * STRB + (jp * 16 + a_col8) * 2);
                ldsm4t(vh, sb + SM_VHI + voff);
                ldsm4t(vl, sb + SM_VLO + voff);
                mma16816(oa0[2 * jp],     a0h, vh);
                mma16816(oa0[2 * jp + 1], a0h, vh + 2);
                mma16816(oa1[2 * jp],     a1h, vh);
                mma16816(oa1[2 * jp + 1], a1h, vh + 2);
                mma16816(oa0[2 * jp],     a0h, vl);
                mma16816(oa0[2 * jp + 1], a0h, vl + 2);
                mma16816(oa1[2 * jp],     a1h, vl);
                mma16816(oa1[2 * jp + 1], a1h, vl + 2);
                mma16816(oa0[2 * jp],     a0l, vh);
                mma16816(oa0[2 * jp + 1], a0l, vh + 2);
                mma16816(oa1[2 * jp],     a1l, vh);
                mma16816(oa1[2 * jp + 1], a1l, vh + 2);
            }
        }
    }

    // ---- normalize and store ----
    l0A += __shfl_xor_sync(0xffffffffu, l0A, 1);
    l0A += __shfl_xor_sync(0xffffffffu, l0A, 2);
    l0B += __shfl_xor_sync(0xffffffffu, l0B, 1);
    l0B += __shfl_xor_sync(0xffffffffu, l0B, 2);
    l1A += __shfl_xor_sync(0xffffffffu, l1A, 1);
    l1A += __shfl_xor_sync(0xffffffffu, l1A, 2);
    l1B += __shfl_xor_sync(0xffffffffu, l1B, 1);
    l1B += __shfl_xor_sync(0xffffffffu, l1B, 2);
    const float i0A = 1.0f / l0A, i0B = 1.0f / l0B;
    const float i1A = 1.0f / l1A, i1B = 1.0f / l1B;

    float* ob0A = out + ((size_t)b * SEQ + trow0)      * DMODEL + h * DH;
    float* ob0B = out + ((size_t)b * SEQ + trow0 + 8)  * DMODEL + h * DH;
    float* ob1A = out + ((size_t)b * SEQ + trow1)      * DMODEL + h * DH;
    float* ob1B = out + ((size_t)b * SEQ + trow1 + 8)  * DMODEL + h * DH;
#pragma unroll
    for (int j = 0; j < 8; ++j) {
        const int e = j * 8 + cb;
        *(float2*)(ob0A + e) = make_float2(oa0[j][0] * i0A, oa0[j][1] * i0A);
        *(float2*)(ob0B + e) = make_float2(oa0[j][2] * i0B, oa0[j][3] * i0B);
        *(float2*)(ob1A + e) = make_float2(oa1[j][0] * i1A, oa1[j][1] * i1A);
        *(float2*)(ob1B + e) = make_float2(oa1[j][2] * i1B, oa1[j][3] * i1B);
    }
}

extern "C" void kernel_launch(void* const* d_in, const int* in_sizes, int n_in,
                              void* d_out, int out_size)
{
    const float* q = (const float*)d_in[0];
    const float* k = (const float*)d_in[1];
    const float* v = (const float*)d_in[2];
    float* out = (float*)d_out;

    static bool attr_set = false;
    if (!attr_set) {
        cudaFuncSetAttribute(alibi_flash_hmma2_kernel,
                             cudaFuncAttributeMaxDynamicSharedMemorySize, SM_TOTAL);
        attr_set = true;
    }
    dim3 grid(32 /* b*h */, 16 /* q tiles */);
    alibi_flash_hmma2_kernel<<<grid, NT, SM_TOTAL>>>(q, k, v, out);
}

// round 5
// speedup vs baseline: 4.9197x; 1.4139x over previous
#include <cuda_runtime.h>
#include <cuda_fp16.h>
#include <stdint.h>

#define SEQ     2048
#define DMODEL  1024
#define NHEAD   16
#define DH      64
#define BR      128        // q rows per CTA (32 per warp)
#define BC      64         // kv rows per tile
#define NT      128
#define STRB    144        // smem row stride bytes (72 fp16)

// smem byte offsets (tiles: 64 or 128 rows x 144B)
#define SM_QHI  0
#define SM_QLO  18432
#define SM_KHI  36864
#define SM_VHI  46080
#define SM_VLO  55296
#define SM_TOTAL 64512

#define C1  0.18033688f     // 0.125 * log2(e)
#define C0  11.541560f      // 8 * log2(e)

__device__ __forceinline__ uint32_t smem_u32(const void* p) {
    uint32_t a;
    asm("{ .reg .u64 t; cvta.to.shared.u64 t, %1; cvt.u32.u64 %0, t; }" : "=r"(a) : "l"(p));
    return a;
}
__device__ __forceinline__ void ldsm4(uint32_t* r, uint32_t addr) {
    asm volatile("ldmatrix.sync.aligned.m8n8.x4.shared.b16 {%0,%1,%2,%3}, [%4];"
                 : "=r"(r[0]), "=r"(r[1]), "=r"(r[2]), "=r"(r[3]) : "r"(addr));
}
__device__ __forceinline__ void ldsm4t(uint32_t* r, uint32_t addr) {
    asm volatile("ldmatrix.sync.aligned.m8n8.x4.trans.shared.b16 {%0,%1,%2,%3}, [%4];"
                 : "=r"(r[0]), "=r"(r[1]), "=r"(r[2]), "=r"(r[3]) : "r"(addr));
}
__device__ __forceinline__ void mma16816(float* d, const uint32_t* a, const uint32_t* b) {
    asm volatile("mma.sync.aligned.m16n8k16.row.col.f32.f16.f16.f32 "
                 "{%0,%1,%2,%3}, {%4,%5,%6,%7}, {%8,%9}, {%0,%1,%2,%3};"
                 : "+f"(d[0]), "+f"(d[1]), "+f"(d[2]), "+f"(d[3])
                 : "r"(a[0]), "r"(a[1]), "r"(a[2]), "r"(a[3]), "r"(b[0]), "r"(b[1]));
}
// pack two fp32 -> f16x2 (elem0 in low half)
__device__ __forceinline__ uint32_t pack2h(float x0, float x1) {
    uint32_t d;
    asm("cvt.rn.f16x2.f32 %0, %1, %2;" : "=r"(d) : "f"(x1), "f"(x0));
    return d;
}
// split two fp32 into fp16 hi pair + fp16 residual pair
__device__ __forceinline__ void split2h(float x0, float x1, uint32_t& hi, uint32_t& lo) {
    hi = pack2h(x0, x1);
    float h0, h1;
    asm("{ .reg .f16 a,b; mov.b32 {a,b}, %2; cvt.f32.f16 %0, a; cvt.f32.f16 %1, b; }"
        : "=f"(h0), "=f"(h1) : "r"(hi));
    lo = pack2h(x0 - h0, x1 - h1);
}
__device__ __forceinline__ float ex2(float x) {
    float y;
    asm("ex2.approx.f32 %0, %1;" : "=f"(y) : "f"(x));
    return y;
}

// load [ROWS x 64] fp32 tile -> split fp16 hi/lo smem tiles
template<int ROWS>
__device__ __forceinline__ void load_split(const float* __restrict__ g, char* sm_,
                                           int off_hi, int off_lo, int tid) {
#pragma unroll
    for (int it = 0; it < ROWS / 8; ++it) {
        int i  = tid + it * NT;
        int r  = i >> 4;
        int c4 = (i & 15) << 2;
        float4 v = *(const float4*)(g + (size_t)r * DMODEL + c4);
        uint32_t h0, l0, h1, l1;
        split2h(v.x, v.y, h0, l0);
        split2h(v.z, v.w, h1, l1);
        int off = r * STRB + c4 * 2;
        *(uint2*)(sm_ + off_hi + off) = make_uint2(h0, h1);
        *(uint2*)(sm_ + off_lo + off) = make_uint2(l0, l1);
    }
}
// load [ROWS x 64] fp32 tile -> fp16 hi-only smem tile
template<int ROWS>
__device__ __forceinline__ void load_hi(const float* __restrict__ g, char* sm_,
                                        int off_hi, int tid) {
#pragma unroll
    for (int it = 0; it < ROWS / 8; ++it) {
        int i  = tid + it * NT;
        int r  = i >> 4;
        int c4 = (i & 15) << 2;
        float4 v = *(const float4*)(g + (size_t)r * DMODEL + c4);
        int off = r * STRB + c4 * 2;
        *(uint2*)(sm_ + off_hi + off) = make_uint2(pack2h(v.x, v.y), pack2h(v.z, v.w));
    }
}

// epilogue: P = 2^(S*C1 + d*mh2 - C0), pack fp16 hi only
#define EPILOGUE(sa, ph, trowA, lA, lB, DOMASK)                                        \
    {                                                                                  \
        const float dA = (float)(s0 + cb - (trowA));                                   \
        const float dB = dA - 8.0f;                                                    \
        _Pragma("unroll")                                                              \
        for (int j = 0; j < 8; ++j) {                                                  \
            const float fj = (float)(8 * j);                                           \
            const float eA = fmaf(dA + fj, mh2, -C0);                                  \
            const float eB = fmaf(dB + fj, mh2, -C0);                                  \
            float p00 = ex2(fmaf(sa[j][0], C1, eA));                                   \
            float p01 = ex2(fmaf(sa[j][1], C1, eA + mh2));                             \
            float p10 = ex2(fmaf(sa[j][2], C1, eB));                                   \
            float p11 = ex2(fmaf(sa[j][3], C1, eB + mh2));                             \
            if (DOMASK) {                                                              \
                const int sc = s0 + 8 * j + cb;                                        \
                if (sc     > (trowA))     p00 = 0.0f;                                  \
                if (sc + 1 > (trowA))     p01 = 0.0f;                                  \
                if (sc     > (trowA) + 8) p10 = 0.0f;                                  \
                if (sc + 1 > (trowA) + 8) p11 = 0.0f;                                  \
            }                                                                          \
            lA += p00 + p01;                                                           \
            lB += p10 + p11;                                                           \
            ph[j][0] = pack2h(p00, p01);                                               \
            ph[j][1] = pack2h(p10, p11);                                               \
        }                                                                              \
    }

__global__ __launch_bounds__(NT, 2)
void alibi_flash_h16_kernel(const float* __restrict__ q,
                            const float* __restrict__ k,
                            const float* __restrict__ v,
                            float* __restrict__ out)
{
    extern __shared__ char smem[];
    const uint32_t sb = smem_u32(smem);
    const int tid  = threadIdx.x;
    const int lane = tid & 31;
    const int warp = tid >> 5;
    const int bh = blockIdx.x;
    const int b  = bh >> 4;
    const int h  = bh & 15;
    const int qt = 15 - (int)blockIdx.y;     // heavy tiles first
    const int t0 = qt * BR;
    const int m0 = warp * 32;
    const float mh2 = exp2f(-0.5f * (float)(h + 1)) * 1.44269504f;

    const int a_row  = lane & 15;
    const int a_col8 = (lane >> 4) << 3;
    const int k_row  = (lane & 7) + ((lane & 16) ? 8 : 0);
    const int k_col8 = (lane & 8) ? 8 : 0;

    const int trow0 = t0 + m0 + (lane >> 2);
    const int trow1 = trow0 + 16;
    const int cb    = (lane & 3) << 1;

    // ---- load Q tile (128 rows, split fp16) ----
    load_split<128>(q + ((size_t)b * SEQ + t0) * DMODEL + h * DH, smem, SM_QHI, SM_QLO, tid);

    float oa0[8][4], oa1[8][4];
#pragma unroll
    for (int j = 0; j < 8; ++j)
#pragma unroll
        for (int e = 0; e < 4; ++e) { oa0[j][e] = 0.0f; oa1[j][e] = 0.0f; }
    float l0A = 0.0f, l0B = 0.0f, l1A = 0.0f, l1B = 0.0f;

    const int nkv = 2 * qt + 2;
    for (int st = 0; st < nkv; ++st) {
        if (st) __syncthreads();
        load_hi<64>(k + ((size_t)b * SEQ + st * BC) * DMODEL + h * DH, smem, SM_KHI, tid);
        load_split<64>(v + ((size_t)b * SEQ + st * BC) * DMODEL + h * DH,
                       smem, SM_VHI, SM_VLO, tid);
        __syncthreads();

        // ===== S = (Qhi + Qlo) Khi^T  (2 products, 2 row blocks) =====
        float sa0[8][4], sa1[8][4];
#pragma unroll
        for (int j = 0; j < 8; ++j)
#pragma unroll
            for (int e = 0; e < 4; ++e) { sa0[j][e] = 0.0f; sa1[j][e] = 0.0f; }

#pragma unroll
        for (int kt = 0; kt < 4; ++kt) {
            uint32_t qh0[4], ql0[4], qh1[4], ql1[4];
            const uint32_t qoff = (uint32_t)((m0 + a_row) * STRB + (kt * 16 + a_col8) * 2);
            ldsm4(qh0, sb + SM_QHI + qoff);
            ldsm4(ql0, sb + SM_QLO + qoff);
            ldsm4(qh1, sb + SM_QHI + qoff + 16 * STRB);
            ldsm4(ql1, sb + SM_QLO + qoff + 16 * STRB);
#pragma unroll
            for (int jp = 0; jp < 4; ++jp) {
                uint32_t kh[4];
                const uint32_t koff = (uint32_t)((jp * 16 + k_row) * STRB + (kt * 16 + k_col8) * 2);
                ldsm4(kh, sb + SM_KHI + koff);
                mma16816(sa0[2 * jp],     qh0, kh);
                mma16816(sa0[2 * jp + 1], qh0, kh + 2);
                mma16816(sa1[2 * jp],     qh1, kh);
                mma16816(sa1[2 * jp + 1], qh1, kh + 2);
                mma16816(sa0[2 * jp],     ql0, kh);
                mma16816(sa0[2 * jp + 1], ql0, kh + 2);
                mma16816(sa1[2 * jp],     ql1, kh);
                mma16816(sa1[2 * jp + 1], ql1, kh + 2);
            }
        }

        // ===== epilogue =====
        const int s0 = st * BC;
        uint32_t ph0[8][2], ph1[8][2];
        if (st < 2 * qt) {     // fully-causal tile: no masking needed
            EPILOGUE(sa0, ph0, trow0, l0A, l0B, false)
            EPILOGUE(sa1, ph1, trow1, l1A, l1B, false)
        } else {
            EPILOGUE(sa0, ph0, trow0, l0A, l0B, true)
            EPILOGUE(sa1, ph1, trow1, l1A, l1B, true)
        }

        // ===== O += Phi (Vhi + Vlo)  (2 products, 2 row blocks) =====
#pragma unroll
        for (int kt = 0; kt < 4; ++kt) {
            uint32_t a0[4] = { ph0[2*kt][0], ph0[2*kt][1], ph0[2*kt+1][0], ph0[2*kt+1][1] };
            uint32_t a1[4] = { ph1[2*kt][0], ph1[2*kt][1], ph1[2*kt+1][0], ph1[2*kt+1][1] };
#pragma unroll
            for (int jp = 0; jp < 4; ++jp) {
                uint32_t vh[4], vl[4];
                const uint32_t voff = (uint32_t)((kt * 16 + a_row) * STRB + (jp * 16 + a_col8) * 2);
                ldsm4t(vh, sb + SM_VHI + voff);
                ldsm4t(vl, sb + SM_VLO + voff);
                mma16816(oa0[2 * jp],     a0, vh);
                mma16816(oa0[2 * jp + 1], a0, vh + 2);
                mma16816(oa1[2 * jp],     a1, vh);
                mma16816(oa1[2 * jp + 1], a1, vh + 2);
                mma16816(oa0[2 * jp],     a0, vl);
                mma16816(oa0[2 * jp + 1], a0, vl + 2);
                mma16816(oa1[2 * jp],     a1, vl);
                mma16816(oa1[2 * jp + 1], a1, vl + 2);
            }
        }
    }

    // ---- normalize and store ----
    l0A += __shfl_xor_sync(0xffffffffu, l0A, 1);
    l0A += __shfl_xor_sync(0xffffffffu, l0A, 2);
    l0B += __shfl_xor_sync(0xffffffffu, l0B, 1);
    l0B += __shfl_xor_sync(0xffffffffu, l0B, 2);
    l1A += __shfl_xor_sync(0xffffffffu, l1A, 1);
    l1A += __shfl_xor_sync(0xffffffffu, l1A, 2);
    l1B += __shfl_xor_sync(0xffffffffu, l1B, 1);
    l1B += __shfl_xor_sync(0xffffffffu, l1B, 2);
    const float i0A = 1.0f / l0A, i0B = 1.0f / l0B;
    const float i1A = 1.0f / l1A, i1B = 1.0f / l1B;

    float* ob0A = out + ((size_t)b * SEQ + trow0)      * DMODEL + h * DH;
    float* ob0B = out + ((size_t)b * SEQ + trow0 + 8)  * DMODEL + h * DH;
    float* ob1A = out + ((size_t)b * SEQ + trow1)      * DMODEL + h * DH;
    float* ob1B = out + ((size_t)b * SEQ + trow1 + 8)  * DMODEL + h * DH;
#pragma unroll
    for (int j = 0; j < 8; ++j) {
        const int e = j * 8 + cb;
        *(float2*)(ob0A + e) = make_float2(oa0[j][0] * i0A, oa0[j][1] * i0A);
        *(float2*)(ob0B + e) = make_float2(oa0[j][2] * i0B, oa0[j][3] * i0B);
        *(float2*)(ob1A + e) = make_float2(oa1[j][0] * i1A, oa1[j][1] * i1A);
        *(float2*)(ob1B + e) = make_float2(oa1[j][2] * i1B, oa1[j][3] * i1B);
    }
}

extern "C" void kernel_launch(void* const* d_in, const int* in_sizes, int n_in,
                              void* d_out, int out_size)
{
    const float* q = (const float*)d_in[0];
    const float* k = (const float*)d_in[1];
    const float* v = (const float*)d_in[2];
    float* out = (float*)d_out;

    static bool attr_set = false;
    if (!attr_set) {
        cudaFuncSetAttribute(alibi_flash_h16_kernel,
                             cudaFuncAttributeMaxDynamicSharedMemorySize, SM_TOTAL);
        attr_set = true;
    }
    dim3 grid(32 /* b*h */, 16 /* q tiles */);
    alibi_flash_h16_kernel<<<grid, NT, SM_TOTAL>>>(q, k, v, out);
}